// round 8
// baseline (speedup 1.0000x reference)
#include <cuda_runtime.h>
#include <math.h>

// Problem shape: B=32768, T=512, channels=3, C=128 logits.
#define T_LEN 512
#define LOSS_SCALE 4194304.0f   // 2^22 fixed point for deterministic loss sum

// Integer accumulators => deterministic regardless of CTA order.
__device__ unsigned long long g_loss_acc = 0ULL;
__device__ int                g_score_acc = 0;
__device__ unsigned int       g_done = 0u;

__global__ __launch_bounds__(128) void fused_kernel(
    const float* __restrict__ imu,
    const float* __restrict__ preds,
    const int*   __restrict__ labels_w,   // raw 32-bit view of labels buffer
    float*       __restrict__ out,
    int B)
{
    const int tid  = threadIdx.x;
    const int warp = tid >> 5;
    const int lane = tid & 31;
    const unsigned FULL = 0xffffffffu;

    // Shared: physics window (padded +48 floats so tid=127's halo read stays
    // in-bounds; pad contents are never used) + reduction scratch + task losses.
    __shared__ float s[T_LEN * 3 + 48];
    __shared__ float redf[6][4];
    __shared__ int   redi[2][4];
    __shared__ float lsh[4];

    if (blockIdx.x < (unsigned)B) {
        // ================= PHYSICS: one CTA per window =================
        const int b = blockIdx.x;

        // Coalesced load: 1536 floats = 384 float4.
        const float4* src = reinterpret_cast<const float4*>(imu + (size_t)b * (T_LEN * 3));
        float4* dst = reinterpret_cast<float4*>(s);
#pragma unroll
        for (int i = 0; i < 3; i++) dst[tid + i * 128] = src[tid + i * 128];
        __syncthreads();

        // Each thread: own timesteps t0..t0+3 (12 floats) + halo t0+4..t0+7.
        // 6x LDS.128, conflict-free (bank stride 12 mod 32 covers all banks/phase).
        __align__(16) float f[24];
        const float4* sv = reinterpret_cast<const float4*>(s + 12 * tid);
#pragma unroll
        for (int j = 0; j < 6; j++) *reinterpret_cast<float4*>(f + 4 * j) = sv[j];

        // ---- Pass 1: per-channel sum and max(|w|) over own 4 timesteps ----
        float sum0 = 0.f, sum1 = 0.f, sum2 = 0.f;
        float mx0 = 0.f, mx1 = 0.f, mx2 = 0.f;
#pragma unroll
        for (int i = 0; i < 4; i++) {
            float w0 = f[3 * i], w1 = f[3 * i + 1], w2 = f[3 * i + 2];
            sum0 += w0; sum1 += w1; sum2 += w2;
            mx0 = fmaxf(mx0, fabsf(w0));
            mx1 = fmaxf(mx1, fabsf(w1));
            mx2 = fmaxf(mx2, fabsf(w2));
        }
#pragma unroll
        for (int o = 16; o; o >>= 1) {
            sum0 += __shfl_xor_sync(FULL, sum0, o);
            sum1 += __shfl_xor_sync(FULL, sum1, o);
            sum2 += __shfl_xor_sync(FULL, sum2, o);
            mx0 = fmaxf(mx0, __shfl_xor_sync(FULL, mx0, o));
            mx1 = fmaxf(mx1, __shfl_xor_sync(FULL, mx1, o));
            mx2 = fmaxf(mx2, __shfl_xor_sync(FULL, mx2, o));
        }
        if (lane == 0) {
            redf[0][warp] = sum0; redf[1][warp] = sum1; redf[2][warp] = sum2;
            redf[3][warp] = mx0;  redf[4][warp] = mx1;  redf[5][warp] = mx2;
        }
        __syncthreads();
        const float m0 = (redf[0][0] + redf[0][1] + redf[0][2] + redf[0][3]) * (1.0f / 512.0f);
        const float m1 = (redf[1][0] + redf[1][1] + redf[1][2] + redf[1][3]) * (1.0f / 512.0f);
        const float m2 = (redf[2][0] + redf[2][1] + redf[2][2] + redf[2][3]) * (1.0f / 512.0f);
        const float M0 = fmaxf(fmaxf(redf[3][0], redf[3][1]), fmaxf(redf[3][2], redf[3][3]));
        const float M1 = fmaxf(fmaxf(redf[4][0], redf[4][1]), fmaxf(redf[4][2], redf[4][3]));
        const float M2 = fmaxf(fmaxf(redf[5][0], redf[5][1]), fmaxf(redf[5][2], redf[5][3]));
        __syncthreads();   // redf reads done before reuse below

        // ---- Pass 2: entirely from registers ----
        float tv = 0.f;
        int c0 = 0, c1 = 0, c2 = 0, zc = 0, jc = 0;
        const bool notLast = (tid != 127);
#pragma unroll
        for (int i = 0; i < 4; i++) {
            float w0 = f[3 * i], w1 = f[3 * i + 1], w2 = f[3 * i + 2];
            float d0 = w0 - m0, d1 = w1 - m1, d2 = w2 - m2;
            tv += d0 * d0 + d1 * d1 + d2 * d2;
            c0 += (fabsf(fabsf(w0) - M0) < 0.01f);
            c1 += (fabsf(fabsf(w1) - M1) < 0.01f);
            c2 += (fabsf(fabsf(w2) - M2) < 0.01f);
            // zero crossings (channel 0), pairs t..t+1 for t < 511
            if (notLast || i < 3) {
                float e0 = f[3 * (i + 1)] - m0;   // i+1<=4 -> f[12] = halo
                zc += (d0 * e0 < 0.0f);
            }
            // jerk outliers, t < 508 (tid=127 has no valid t)
            if (notLast) {
#pragma unroll
                for (int c = 0; c < 3; c++) {
                    float a  = f[3 * i + c];
                    float bm = f[3 * (i + 2) + c];
                    float cm = f[3 * (i + 4) + c];   // i+4<=7 -> halo
                    float vA = (bm - a) * 25.0f;
                    float vB = (cm - bm) * 25.0f;
                    jc += (fabsf((vB - vA) * 25.0f) > 5000.0f);
                }
            }
        }
        // Pack counters: c* <= 512 (10 bits), zc <= 511, jc <= 1524.
        int pa = c0 | (c1 << 10) | (c2 << 20);
        int pb = zc | (jc << 16);
#pragma unroll
        for (int o = 16; o; o >>= 1) {
            tv += __shfl_xor_sync(FULL, tv, o);
            pa += __shfl_xor_sync(FULL, pa, o);
            pb += __shfl_xor_sync(FULL, pb, o);
        }
        if (lane == 0) {
            redf[0][warp] = tv;
            redi[0][warp] = pa;
            redi[1][warp] = pb;
        }
        __syncthreads();

        if (tid == 0) {
            float tvT = (redf[0][0] + redf[0][1] + redf[0][2] + redf[0][3]) * (1.0f / 512.0f);
            int paT = redi[0][0] + redi[0][1] + redi[0][2] + redi[0][3];
            int pbT = redi[1][0] + redi[1][1] + redi[1][2] + redi[1][3];
            int cc0 = paT & 1023, cc1 = (paT >> 10) & 1023, cc2 = (paT >> 20) & 1023;
            int zcc = pbT & 0xffff, jcc = pbT >> 16;

            bool reject = tvT < 0.005f;
            reject |= (M0 >= 0.5f) && ((float)cc0 * (1.0f / 512.0f) > 0.2f);
            reject |= (M1 >= 0.5f) && ((float)cc1 * (1.0f / 512.0f) > 0.2f);
            reject |= (M2 >= 0.5f) && ((float)cc2 * (1.0f / 512.0f) > 0.2f);
            reject |= (jcc >= 77);   // js[1447] > 5000  <=>  count(>5000) >= 77

            float s1 = tvT > 10.0f ? 90.0f : (tvT > 2.0f ? 80.0f : (tvT > 0.5f ? 70.0f : 58.0f));
            float zcr = (float)zcc * (1.0f / 512.0f);
            float s2 = zcr > 0.15f ? 85.0f : (zcr > 0.07f ? 70.0f : 55.0f);
            int score = (int)floorf((s1 + s2) * 0.5f);
            if (!reject) atomicAdd(&g_score_acc, score);
        }
        __syncthreads();
    } else {
        // ================= TASK LOSS: 4 rows per CTA (1 warp/row) =========
        const int idx = blockIdx.x - B;
        const int row = idx * 4 + warp;

        // Labels dtype detection from first 128 words (L2-hit after CTA 0):
        // int64 little-endian => all odd words (high halves of values <128) == 0.
        int a = labels_w[2 * lane + 1] | labels_w[2 * (lane + 32) + 1];
#pragma unroll
        for (int o = 16; o; o >>= 1) a |= __shfl_xor_sync(FULL, a, o);
        const int is64 = (a == 0);

        if (row < B) {
            const float4* p4 = reinterpret_cast<const float4*>(preds + (size_t)row * 128);
            float4 v = p4[lane];
            float mx = fmaxf(fmaxf(v.x, v.y), fmaxf(v.z, v.w));
#pragma unroll
            for (int o = 16; o; o >>= 1) mx = fmaxf(mx, __shfl_xor_sync(FULL, mx, o));
            float sum = expf(v.x - mx) + expf(v.y - mx) + expf(v.z - mx) + expf(v.w - mx);
#pragma unroll
            for (int o = 16; o; o >>= 1) sum += __shfl_xor_sync(FULL, sum, o);
            if (lane == 0) {
                int lbl = is64 ? labels_w[2 * (size_t)row] : labels_w[row];
                float pl = preds[(size_t)row * 128 + lbl];
                lsh[warp] = logf(sum) + mx - pl;   // -(pl - logsumexp) >= 0
            }
        } else if (lane == 0) {
            lsh[warp] = 0.f;
        }
        __syncthreads();
        if (tid == 0) {
            unsigned long long acc = 0ULL;
#pragma unroll
            for (int j = 0; j < 4; j++)
                acc += (unsigned long long)llrintf(lsh[j] * LOSS_SCALE);
            atomicAdd(&g_loss_acc, acc);
        }
        __syncthreads();
    }

    // ============ Last-CTA finalize (deterministic: integer sums) ============
    if (tid == 0) {
        __threadfence();
        unsigned int done = atomicAdd(&g_done, 1u);
        if (done == gridDim.x - 1) {
            unsigned long long L = atomicAdd(&g_loss_acc, 0ULL);
            int S = atomicAdd(&g_score_acc, 0);
            double task = (double)L / ((double)LOSS_SCALE * (double)B);
            double pen  = 1.0 - (double)S / (100.0 * (double)B);
            out[0] = (float)(task + 0.3 * pen);
            // Reset state so the captured graph replays identically.
            atomicExch(&g_loss_acc, 0ULL);
            atomicExch(&g_score_acc, 0);
            __threadfence();
            atomicExch(&g_done, 0u);
        }
    }
}

// ---------------------------------------------------------------------------
extern "C" void kernel_launch(void* const* d_in, const int* in_sizes, int n_in,
                              void* d_out, int out_size) {
    const float* preds    = (const float*)d_in[0];
    const int*   labels_w = (const int*)d_in[1];
    const float* imu      = (const float*)d_in[2];
    const int B = in_sizes[1];            // 32768

    const int grid = B + (B + 3) / 4;     // physics CTAs + task CTAs
    fused_kernel<<<grid, 128>>>(imu, preds, labels_w, (float*)d_out, B);
}

// round 9
// speedup vs baseline: 1.0039x; 1.0039x over previous
#include <cuda_runtime.h>
#include <math.h>

// Problem shape: B=32768, T=512, channels=3, C=128 logits.
#define T_LEN 512
#define WPB 8                    // warps (=windows or task-rows) per CTA
#define LOSS_SCALE 4194304.0f    // 2^22 fixed point => deterministic loss sum

__device__ unsigned long long g_loss_acc = 0ULL;
__device__ int                g_score_acc = 0;
__device__ unsigned int       g_done = 0u;

__global__ __launch_bounds__(256, 3) void fused_kernel(
    const float* __restrict__ imu,
    const float* __restrict__ preds,
    const int*   __restrict__ labels_w,   // raw 32-bit view of labels buffer
    float*       __restrict__ out,
    int B, int physCtas)
{
    __shared__ float smem[WPB * T_LEN * 3];   // 48 KB: one 6KB window per warp
    const int tid  = threadIdx.x;
    const int warp = tid >> 5;
    const int lane = tid & 31;
    const unsigned FULL = 0xffffffffu;

    if ((int)blockIdx.x < physCtas) {
        // ================= PHYSICS: one window per WARP =================
        const int b = blockIdx.x * WPB + warp;
        if (b < B) {
            float4* sw4 = reinterpret_cast<float4*>(smem + warp * (T_LEN * 3));
            const float4* src =
                reinterpret_cast<const float4*>(imu + (size_t)b * (T_LEN * 3));

            // Stage: coalesced LDG (MLP=12) -> linear smem.
            float4 v[12];
#pragma unroll
            for (int k = 0; k < 12; k++) v[k] = src[lane + 32 * k];
#pragma unroll
            for (int k = 0; k < 12; k++) sw4[lane + 32 * k] = v[k];
            __syncwarp();

            // Own 16 timesteps = 48 floats = 12 LDS.128 (conflict-free:
            // float4 index 12*lane -> banks 12*lane mod 32, distinct per phase).
            float f[48];
#pragma unroll
            for (int j = 0; j < 12; j++)
                *reinterpret_cast<float4*>(f + 4 * j) = sw4[12 * lane + j];

            // ---- Pass 1: per-channel sum, sum-of-squares, max|w| ----
            float s0 = 0.f, s1 = 0.f, s2 = 0.f, q = 0.f;
            float M0 = 0.f, M1 = 0.f, M2 = 0.f;
#pragma unroll
            for (int t = 0; t < 16; t++) {
                float w0 = f[3 * t], w1 = f[3 * t + 1], w2 = f[3 * t + 2];
                s0 += w0; s1 += w1; s2 += w2;
                q = fmaf(w0, w0, q); q = fmaf(w1, w1, q); q = fmaf(w2, w2, q);
                M0 = fmaxf(M0, fabsf(w0));
                M1 = fmaxf(M1, fabsf(w1));
                M2 = fmaxf(M2, fabsf(w2));
            }
#pragma unroll
            for (int o = 16; o; o >>= 1) {
                s0 += __shfl_xor_sync(FULL, s0, o);
                s1 += __shfl_xor_sync(FULL, s1, o);
                s2 += __shfl_xor_sync(FULL, s2, o);
                q  += __shfl_xor_sync(FULL, q, o);
                M0 = fmaxf(M0, __shfl_xor_sync(FULL, M0, o));
                M1 = fmaxf(M1, __shfl_xor_sync(FULL, M1, o));
                M2 = fmaxf(M2, __shfl_xor_sync(FULL, M2, o));
            }
            const float m0 = s0 * (1.0f / 512.0f);
            const float m1 = s1 * (1.0f / 512.0f);
            const float m2 = s2 * (1.0f / 512.0f);
            // tv = (sum w^2 - n*sum m^2)/n ; n*m^2 << sum w^2, no cancellation risk
            const float tv = q * (1.0f / 512.0f) - (m0 * m0 + m1 * m1 + m2 * m2);

            // Halo: first 4 timesteps (12 floats) of lane+1 (lane 31: none needed
            // for jerk; masked for zc).
            float h[12];
            {
                const int hl = (lane < 31) ? lane + 1 : lane;
#pragma unroll
                for (int j = 0; j < 3; j++)
                    *reinterpret_cast<float4*>(h + 4 * j) = sw4[12 * hl + j];
            }

            // ---- Pass 2: at_max (skipped when impossible), zc, jerk ----
            int c0 = 0, c1 = 0, c2 = 0, zc = 0, jc = 0;
            const bool needAM = (M0 >= 0.5f) || (M1 >= 0.5f) || (M2 >= 0.5f);
            if (needAM) {     // warp-uniform, rare (~0.1% of windows)
#pragma unroll
                for (int t = 0; t < 16; t++) {
                    c0 += (fabsf(fabsf(f[3 * t])     - M0) < 0.01f);
                    c1 += (fabsf(fabsf(f[3 * t + 1]) - M1) < 0.01f);
                    c2 += (fabsf(fabsf(f[3 * t + 2]) - M2) < 0.01f);
                }
            }
#pragma unroll
            for (int t = 0; t < 16; t++) {
                // zero crossings, channel 0: pair (t_g, t_g+1), t_g < 511
                float d0  = f[3 * t] - m0;
                float d0n = ((t < 15) ? f[3 * t + 3] : h[0]) - m0;
                if (t < 15 || lane < 31) zc += (d0 * d0n < 0.0f);
                // jerk: |w[t] - 2w[t+2] + w[t+4]| > 8  (== |jerk|>5000), t_g < 508
                if (t < 12 || lane < 31) {
#pragma unroll
                    for (int c = 0; c < 3; c++) {
                        const int i2 = 3 * (t + 2) + c, i4 = 3 * (t + 4) + c;
                        float a  = f[3 * t + c];
                        float bb = (i2 < 48) ? f[i2] : h[i2 - 48];
                        float cc = (i4 < 48) ? f[i4] : h[i4 - 48];
                        float jv = fmaf(-2.0f, bb, a + cc);
                        jc += (fabsf(jv) > 8.0f);
                    }
                }
            }
            // Pack: c* <= 512 (10 bits), zc <= 511, jc <= 1524.
            int pa = c0 | (c1 << 10) | (c2 << 20);
            int pb = zc | (jc << 16);
#pragma unroll
            for (int o = 16; o; o >>= 1) {
                pa += __shfl_xor_sync(FULL, pa, o);
                pb += __shfl_xor_sync(FULL, pb, o);
            }

            if (lane == 0) {
                int cc0 = pa & 1023, cc1 = (pa >> 10) & 1023, cc2 = (pa >> 20) & 1023;
                int zcc = pb & 0xffff, jcc = pb >> 16;

                bool reject = tv < 0.005f;
                reject |= (M0 >= 0.5f) && ((float)cc0 * (1.0f / 512.0f) > 0.2f);
                reject |= (M1 >= 0.5f) && ((float)cc1 * (1.0f / 512.0f) > 0.2f);
                reject |= (M2 >= 0.5f) && ((float)cc2 * (1.0f / 512.0f) > 0.2f);
                reject |= (jcc >= 77);   // js[1447]>5000 <=> count(>5000) >= 77

                float s1v = tv > 10.0f ? 90.0f
                          : (tv > 2.0f ? 80.0f : (tv > 0.5f ? 70.0f : 58.0f));
                float zcr = (float)zcc * (1.0f / 512.0f);
                float s2v = zcr > 0.15f ? 85.0f : (zcr > 0.07f ? 70.0f : 55.0f);
                int score = (int)floorf((s1v + s2v) * 0.5f);
                if (!reject) atomicAdd(&g_score_acc, score);
            }
        }
    } else {
        // ================= TASK LOSS: one row per warp, 8 rows/CTA ========
        const int row = ((int)blockIdx.x - physCtas) * WPB + warp;
        float* lsh = smem;   // reuse window smem for per-warp losses

        // Labels dtype detect from first 128 words (L2-hit after first CTA):
        // int64 LE => all odd words (high halves of values < 128) are zero.
        int a = labels_w[2 * lane + 1] | labels_w[2 * (lane + 32) + 1];
#pragma unroll
        for (int o = 16; o; o >>= 1) a |= __shfl_xor_sync(FULL, a, o);
        const int is64 = (a == 0);

        if (row < B) {
            const float4* p4 =
                reinterpret_cast<const float4*>(preds + (size_t)row * 128);
            float4 vv = p4[lane];
            float mx = fmaxf(fmaxf(vv.x, vv.y), fmaxf(vv.z, vv.w));
#pragma unroll
            for (int o = 16; o; o >>= 1) mx = fmaxf(mx, __shfl_xor_sync(FULL, mx, o));
            float sum = __expf(vv.x - mx) + __expf(vv.y - mx) +
                        __expf(vv.z - mx) + __expf(vv.w - mx);
#pragma unroll
            for (int o = 16; o; o >>= 1) sum += __shfl_xor_sync(FULL, sum, o);
            if (lane == 0) {
                int lbl = is64 ? labels_w[2 * (size_t)row] : labels_w[row];
                float pl = preds[(size_t)row * 128 + lbl];
                lsh[warp] = __logf(sum) + mx - pl;   // -(pl - logsumexp)
            }
        } else if (lane == 0) {
            lsh[warp] = 0.f;
        }
        __syncthreads();
        if (tid == 0) {
            unsigned long long acc = 0ULL;
#pragma unroll
            for (int j = 0; j < WPB; j++)
                acc += (unsigned long long)llrintf(lsh[j] * LOSS_SCALE);
            atomicAdd(&g_loss_acc, acc);
        }
    }

    // ============ Last-CTA finalize (deterministic: integer sums) ============
    if (tid == 0) {
        __threadfence();
        unsigned int done = atomicAdd(&g_done, 1u);
        if (done == gridDim.x - 1) {
            unsigned long long L = atomicAdd(&g_loss_acc, 0ULL);
            int S = atomicAdd(&g_score_acc, 0);
            double task = (double)L / ((double)LOSS_SCALE * (double)B);
            double pen  = 1.0 - (double)S / (100.0 * (double)B);
            out[0] = (float)(task + 0.3 * pen);
            // Reset so the captured graph replays identically.
            atomicExch(&g_loss_acc, 0ULL);
            atomicExch(&g_score_acc, 0);
            __threadfence();
            atomicExch(&g_done, 0u);
        }
    }
}

// ---------------------------------------------------------------------------
extern "C" void kernel_launch(void* const* d_in, const int* in_sizes, int n_in,
                              void* d_out, int out_size) {
    const float* preds    = (const float*)d_in[0];
    const int*   labels_w = (const int*)d_in[1];
    const float* imu      = (const float*)d_in[2];
    const int B = in_sizes[1];                 // 32768

    const int physCtas = (B + WPB - 1) / WPB;  // 4096
    const int taskCtas = (B + WPB - 1) / WPB;  // 4096
    fused_kernel<<<physCtas + taskCtas, 256>>>(imu, preds, labels_w,
                                               (float*)d_out, B, physCtas);
}